// round 4
// baseline (speedup 1.0000x reference)
#include <cuda_runtime.h>
#include <math.h>
#include <limits.h>

#define SS 7
#define NPTS 49
#define CCH 256
#define TILE_MAX 448
#define NOFF 14   // ceil(TILE_MAX/32)

// Per-point tap computation, identical math to the reference.
__device__ __forceinline__ void compute_tap(
    const float* __restrict__ r, int tid, int H, float scale,
    int& x0, int& x1, int& y0, int& y1,
    float& w00, float& w01, float& w10, float& w11)
{
    const float x = r[0], y = r[1], w = r[2], h = r[3], a = r[4], b = r[5];

    const float d1 = sqrtf(4.f * a * a + h * h);   // |v3 - v1|
    const float d2 = sqrtf(w * w + 4.f * b * b);   // |v4 - v2|
    const float eps = 1e-6f;
    float V0x, V0y, V1x, V1y, V2x, V2y;
    if (d1 > d2) {
        const float sA = d1 / (d2 + eps);
        V0x = x + a;          V0y = y + 0.5f * h;
        V1x = (x + 0.5f * w) + (sA - 1.f) * (0.5f * w);
        V1y = (y + b)        + (sA - 1.f) * b;
        V2x = x - a;          V2y = y - 0.5f * h;
    } else {
        const float sB = d2 / (d1 + eps);
        V0x = (x + a)        + (sB - 1.f) * a;
        V0y = (y + 0.5f * h) + (sB - 1.f) * (0.5f * h);
        V1x = x + 0.5f * w;   V1y = y + b;
        V2x = (x - a)        - (sB - 1.f) * a;
        V2y = (y - 0.5f * h) - (sB - 1.f) * (0.5f * h);
    }
    const float hre = sqrtf((V1x - V0x) * (V1x - V0x) + (V1y - V0y) * (V1y - V0y));
    const float wre = sqrtf((V2x - V1x) * (V2x - V1x) + (V2y - V1y) * (V2y - V1y));
    float theta = atan2f(V1y - V2y, V1x - V2x);
    const float PI2 = 1.5707963267948966f;
    theta = fminf(fmaxf(theta, -PI2), PI2);
    const float ct = cosf(theta), st = sinf(theta);

    const int   i  = tid / SS, j = tid % SS;
    const float tj = (float)j / 6.f - 0.5f;
    const float ti = (float)i / 6.f - 0.5f;
    const float gx = wre * scale * tj;
    const float gy = hre * scale * ti;
    const float rx =  gx * ct + gy * st + x * scale;
    const float ry = -gx * st + gy * ct + y * scale;

    const float Wf  = (float)H;
    const float inv = 1.f / (float)(H - 1);
    const float gxn = rx * scale * inv * 2.f - 1.f;
    const float gyn = ry * scale * inv * 2.f - 1.f;
    const float px = ((gxn + 1.f) * Wf - 1.f) * 0.5f;
    const float py = ((gyn + 1.f) * Wf - 1.f) * 0.5f;

    const float x0f = floorf(px), y0f = floorf(py);
    const float wx = px - x0f, wy = py - y0f;
    x0 = min(max((int)x0f, 0), H - 1);
    x1 = min(x0 + 1, H - 1);
    y0 = min(max((int)y0f, 0), H - 1);
    y1 = min(y0 + 1, H - 1);
    w00 = (1.f - wx) * (1.f - wy);
    w01 = wx * (1.f - wy);
    w10 = (1.f - wx) * wy;
    w11 = wx * wy;
}

// ---------------- Kernel A: gather path, levels 1-3 ----------------
__global__ __launch_bounds__(256) void roi_align_gather_kernel(
    const float* __restrict__ f1, const float* __restrict__ f2,
    const float* __restrict__ f3,
    const float* __restrict__ rois, const int* __restrict__ levels,
    float* __restrict__ out, int N)
{
    const int roi = blockIdx.x;
    const int lvl = __ldg(levels + roi);
    if (lvl == 0) return;

    const int bb  = roi / N;
    const int tid = threadIdx.x;

    __shared__ float s_w00[NPTS], s_w01[NPTS], s_w10[NPTS], s_w11[NPTS];
    __shared__ int   s_o00[NPTS], s_o01[NPTS], s_o10[NPTS], s_o11[NPTS];

    int H; float scale; const float* fbase;
    switch (lvl) {
        case 1:  H = 128; scale = 0.125f;    fbase = f1; break;
        case 2:  H = 64;  scale = 0.0625f;   fbase = f2; break;
        default: H = 32;  scale = 0.03125f;  fbase = f3; break;
    }
    const int HW = H * H;
    const float* base = fbase + (size_t)bb * CCH * HW;
    float* op = out + (size_t)roi * CCH * NPTS;

    if (tid < NPTS) {
        int x0, x1, y0, y1; float w00, w01, w10, w11;
        compute_tap(rois + (size_t)roi * 6, tid, H, scale,
                    x0, x1, y0, y1, w00, w01, w10, w11);
        s_o00[tid] = y0 * H + x0;
        s_o01[tid] = y0 * H + x1;
        s_o10[tid] = y1 * H + x0;
        s_o11[tid] = y1 * H + x1;
        s_w00[tid] = w00; s_w01[tid] = w01; s_w10[tid] = w10; s_w11[tid] = w11;
    }
    __syncthreads();

    const int warp = tid >> 5;
    const int lane = tid & 31;

    const int  pA = lane;
    const bool hasB = (32 + lane) < NPTS;
    const int  pB = hasB ? 32 + lane : 0;

    const int   a00 = s_o00[pA], a01 = s_o01[pA], a10 = s_o10[pA], a11 = s_o11[pA];
    const float wa00 = s_w00[pA], wa01 = s_w01[pA], wa10 = s_w10[pA], wa11 = s_w11[pA];
    const int   b00 = s_o00[pB], b01 = s_o01[pB], b10 = s_o10[pB], b11 = s_o11[pB];
    const float wb00 = s_w00[pB], wb01 = s_w01[pB], wb10 = s_w10[pB], wb11 = s_w11[pB];

    #pragma unroll 1
    for (int c = warp; c < CCH; c += 16) {
        const float* pl0 = base + (size_t)c * HW;
        const float* pl1 = pl0 + (size_t)8 * HW;
        float* o0 = op + c * NPTS;
        float* o1 = o0 + 8 * NPTS;

        const float v0a00 = __ldg(pl0 + a00), v0a01 = __ldg(pl0 + a01);
        const float v0a10 = __ldg(pl0 + a10), v0a11 = __ldg(pl0 + a11);
        const float v1a00 = __ldg(pl1 + a00), v1a01 = __ldg(pl1 + a01);
        const float v1a10 = __ldg(pl1 + a10), v1a11 = __ldg(pl1 + a11);

        float v0b00 = 0.f, v0b01 = 0.f, v0b10 = 0.f, v0b11 = 0.f;
        float v1b00 = 0.f, v1b01 = 0.f, v1b10 = 0.f, v1b11 = 0.f;
        if (hasB) {
            v0b00 = __ldg(pl0 + b00); v0b01 = __ldg(pl0 + b01);
            v0b10 = __ldg(pl0 + b10); v0b11 = __ldg(pl0 + b11);
            v1b00 = __ldg(pl1 + b00); v1b01 = __ldg(pl1 + b01);
            v1b10 = __ldg(pl1 + b10); v1b11 = __ldg(pl1 + b11);
        }

        o0[pA] = v0a00 * wa00 + v0a01 * wa01 + v0a10 * wa10 + v0a11 * wa11;
        o1[pA] = v1a00 * wa00 + v1a01 * wa01 + v1a10 * wa10 + v1a11 * wa11;
        if (hasB) {
            o0[pB] = v0b00 * wb00 + v0b01 * wb01 + v0b10 * wb10 + v0b11 * wb11;
            o1[pB] = v1b00 * wb00 + v1b01 * wb01 + v1b10 * wb10 + v1b11 * wb11;
        }
    }
}

// ---------------- Kernel B: tile path, level 0 ----------------
__global__ __launch_bounds__(256) void roi_align_tile0_kernel(
    const float* __restrict__ f0,
    const float* __restrict__ rois, const int* __restrict__ levels,
    float* __restrict__ out, int N)
{
    const int roi = blockIdx.x;
    const int lvl = __ldg(levels + roi);
    if (lvl != 0) return;

    const int bb  = roi / N;
    const int tid = threadIdx.x;
    const int H = 256;
    const float scale = 0.25f;
    const int HW = H * H;

    __shared__ float s_w00[NPTS], s_w01[NPTS], s_w10[NPTS], s_w11[NPTS];
    __shared__ int   s_off[NPTS], s_dx[NPTS], s_dyw[NPTS];
    __shared__ int   s_bbox[4];
    __shared__ float s_tile[8][2][TILE_MAX];

    const float* base = f0 + (size_t)bb * CCH * HW;
    float* op = out + (size_t)roi * CCH * NPTS;

    if (tid == 0) {
        s_bbox[0] = INT_MAX; s_bbox[1] = INT_MAX;
        s_bbox[2] = 0;       s_bbox[3] = 0;
    }
    __syncthreads();

    int x0 = 0, x1 = 0, y0 = 0, y1 = 0;
    if (tid < NPTS) {
        float w00, w01, w10, w11;
        compute_tap(rois + (size_t)roi * 6, tid, H, scale,
                    x0, x1, y0, y1, w00, w01, w10, w11);
        s_w00[tid] = w00; s_w01[tid] = w01; s_w10[tid] = w10; s_w11[tid] = w11;
        atomicMin(&s_bbox[0], x0);
        atomicMin(&s_bbox[1], y0);
        atomicMax(&s_bbox[2], x1);
        atomicMax(&s_bbox[3], y1);
    }
    __syncthreads();

    const int xlo = s_bbox[0], ylo = s_bbox[1];
    const int TW = s_bbox[2] - xlo + 1;
    const int TS = TW * (s_bbox[3] - ylo + 1);
    const bool big = (TS > TILE_MAX);   // mathematically never; safety only

    if (tid < NPTS) {
        if (!big) {
            s_off[tid] = (y0 - ylo) * TW + (x0 - xlo);
            s_dx[tid]  = x1 - x0;
            s_dyw[tid] = (y1 - y0) * TW;
        } else {
            s_off[tid] = y0 * H + x0;
            s_dx[tid]  = x1 - x0;
            s_dyw[tid] = (y1 - y0) * H;
        }
    }
    __syncthreads();

    const int warp = tid >> 5;
    const int lane = tid & 31;

    const int  pA = lane;
    const bool hasB = (32 + lane) < NPTS;
    const int  pB = hasB ? 32 + lane : 0;

    const float wa00 = s_w00[pA], wa01 = s_w01[pA], wa10 = s_w10[pA], wa11 = s_w11[pA];
    const int   offA = s_off[pA], dxA = s_dx[pA], dywA = s_dyw[pA];
    const float wb00 = s_w00[pB], wb01 = s_w01[pB], wb10 = s_w10[pB], wb11 = s_w11[pB];
    const int   offB = s_off[pB], dxB = s_dx[pB], dywB = s_dyw[pB];

    if (!big) {
        // Precompute this lane's global tile offsets into registers (no smem indirection).
        int gof[NOFF];
        #pragma unroll
        for (int k = 0; k < NOFF; k++) {
            const int idx = lane + 32 * k;
            if (idx < TS) {
                const int ty = idx / TW;
                gof[k] = (ylo + ty) * H + xlo + (idx - ty * TW);
            } else {
                gof[k] = 0;
            }
        }

        float* tA = &s_tile[warp][0][0];
        float* tB = &s_tile[warp][1][0];

        #pragma unroll 1
        for (int c = warp; c < CCH; c += 16) {
            const float* pl0 = base + (size_t)c * HW;
            const float* pl1 = pl0 + (size_t)8 * HW;

            float v0[NOFF], v1[NOFF];
            #pragma unroll
            for (int k = 0; k < NOFF; k++) {
                if (lane + 32 * k < TS) {
                    v0[k] = __ldg(pl0 + gof[k]);
                    v1[k] = __ldg(pl1 + gof[k]);
                }
            }
            #pragma unroll
            for (int k = 0; k < NOFF; k++) {
                const int idx = lane + 32 * k;
                if (idx < TS) { tA[idx] = v0[k]; tB[idx] = v1[k]; }
            }
            __syncwarp();

            float* o0 = op + c * NPTS;
            float* o1 = o0 + 8 * NPTS;
            o0[pA] = tA[offA] * wa00 + tA[offA + dxA] * wa01
                   + tA[offA + dywA] * wa10 + tA[offA + dxA + dywA] * wa11;
            o1[pA] = tB[offA] * wa00 + tB[offA + dxA] * wa01
                   + tB[offA + dywA] * wa10 + tB[offA + dxA + dywA] * wa11;
            if (hasB) {
                o0[pB] = tA[offB] * wb00 + tA[offB + dxB] * wb01
                       + tA[offB + dywB] * wb10 + tA[offB + dxB + dywB] * wb11;
                o1[pB] = tB[offB] * wb00 + tB[offB + dxB] * wb01
                       + tB[offB + dywB] * wb10 + tB[offB + dxB + dywB] * wb11;
            }
            __syncwarp();
        }
    } else {
        // Fallback direct gather (absolute offsets).
        #pragma unroll 1
        for (int c = warp; c < CCH; c += 8) {
            const float* pl = base + (size_t)c * HW;
            float* o = op + c * NPTS;
            o[pA] = __ldg(pl + offA) * wa00 + __ldg(pl + offA + dxA) * wa01
                  + __ldg(pl + offA + dywA) * wa10 + __ldg(pl + offA + dxA + dywA) * wa11;
            if (hasB) {
                o[pB] = __ldg(pl + offB) * wb00 + __ldg(pl + offB + dxB) * wb01
                      + __ldg(pl + offB + dywB) * wb10 + __ldg(pl + offB + dxB + dywB) * wb11;
            }
        }
    }
}

extern "C" void kernel_launch(void* const* d_in, const int* in_sizes, int n_in,
                              void* d_out, int out_size) {
    const float* f0 = (const float*)d_in[0];
    const float* f1 = (const float*)d_in[1];
    const float* f2 = (const float*)d_in[2];
    const float* f3 = (const float*)d_in[3];
    const float* rois = (const float*)d_in[4];
    const int* levels = (const int*)d_in[5];
    float* out = (float*)d_out;

    const int B = in_sizes[0] / (256 * 256 * 256);
    const int total = in_sizes[5];        // B*N rois
    const int N = total / (B > 0 ? B : 1);

    roi_align_tile0_kernel<<<total, 256>>>(f0, rois, levels, out, N);
    roi_align_gather_kernel<<<total, 256>>>(f1, f2, f3, rois, levels, out, N);
}

// round 5
// speedup vs baseline: 1.3109x; 1.3109x over previous
#include <cuda_runtime.h>
#include <math.h>

#define SS 7
#define NPTS 49
#define CCH 256
#define CSPLIT 2          // CTAs per ROI
#define CPER (CCH / CSPLIT)

__global__ __launch_bounds__(256) void oriented_roi_align_kernel(
    const float* __restrict__ f0, const float* __restrict__ f1,
    const float* __restrict__ f2, const float* __restrict__ f3,
    const float* __restrict__ rois, const int* __restrict__ levels,
    float* __restrict__ out, int N)
{
    const int roi  = blockIdx.x >> 1;     // roi = b*N + n
    const int half = blockIdx.x & 1;      // which channel half
    const int bb   = roi / N;
    const int tid  = threadIdx.x;

    __shared__ float s_w00[NPTS], s_w01[NPTS], s_w10[NPTS], s_w11[NPTS];
    __shared__ int   s_o00[NPTS], s_o01[NPTS], s_o10[NPTS], s_o11[NPTS];

    const int lvl = __ldg(levels + roi);
    int H; float scale; const float* fbase;
    switch (lvl) {
        case 0:  H = 256; scale = 0.25f;     fbase = f0; break;
        case 1:  H = 128; scale = 0.125f;    fbase = f1; break;
        case 2:  H = 64;  scale = 0.0625f;   fbase = f2; break;
        default: H = 32;  scale = 0.03125f;  fbase = f3; break;
    }
    const int HW = H * H;
    const float* base = fbase + (size_t)bb * CCH * HW;
    float* op = out + (size_t)roi * CCH * NPTS;

    if (tid < NPTS) {
        const float* r = rois + (size_t)roi * 6;
        const float x = r[0], y = r[1], w = r[2], h = r[3], a = r[4], b = r[5];

        // ---- parallelogram -> rectangle (matches reference) ----
        const float d1 = sqrtf(4.f * a * a + h * h);   // |v3 - v1|
        const float d2 = sqrtf(w * w + 4.f * b * b);   // |v4 - v2|
        const float eps = 1e-6f;
        float V0x, V0y, V1x, V1y, V2x, V2y;
        if (d1 > d2) {
            const float sA = d1 / (d2 + eps);
            V0x = x + a;          V0y = y + 0.5f * h;
            V1x = (x + 0.5f * w) + (sA - 1.f) * (0.5f * w);
            V1y = (y + b)        + (sA - 1.f) * b;
            V2x = x - a;          V2y = y - 0.5f * h;
        } else {
            const float sB = d2 / (d1 + eps);
            V0x = (x + a)        + (sB - 1.f) * a;
            V0y = (y + 0.5f * h) + (sB - 1.f) * (0.5f * h);
            V1x = x + 0.5f * w;   V1y = y + b;
            V2x = (x - a)        - (sB - 1.f) * a;
            V2y = (y - 0.5f * h) - (sB - 1.f) * (0.5f * h);
        }
        const float hre = sqrtf((V1x - V0x) * (V1x - V0x) + (V1y - V0y) * (V1y - V0y));
        const float wre = sqrtf((V2x - V1x) * (V2x - V1x) + (V2y - V1y) * (V2y - V1y));
        float theta = atan2f(V1y - V2y, V1x - V2x);
        const float PI2 = 1.5707963267948966f;
        theta = fminf(fmaxf(theta, -PI2), PI2);
        const float ct = cosf(theta), st = sinf(theta);

        // ---- sample point for this (i, j) ----
        const int   i  = tid / SS, j = tid % SS;
        const float tj = (float)j / 6.f - 0.5f;
        const float ti = (float)i / 6.f - 0.5f;
        const float gx = wre * scale * tj;
        const float gy = hre * scale * ti;
        const float rx =  gx * ct + gy * st + x * scale;
        const float ry = -gx * st + gy * ct + y * scale;

        const float Wf  = (float)H;
        const float inv = 1.f / (float)(H - 1);
        const float gxn = rx * scale * inv * 2.f - 1.f;
        const float gyn = ry * scale * inv * 2.f - 1.f;
        const float px = ((gxn + 1.f) * Wf - 1.f) * 0.5f;
        const float py = ((gyn + 1.f) * Wf - 1.f) * 0.5f;

        const float x0f = floorf(px), y0f = floorf(py);
        const float wx = px - x0f, wy = py - y0f;
        const int x0 = min(max((int)x0f, 0), H - 1);
        const int x1 = min(x0 + 1, H - 1);
        const int y0 = min(max((int)y0f, 0), H - 1);
        const int y1 = min(y0 + 1, H - 1);

        s_o00[tid] = y0 * H + x0;
        s_o01[tid] = y0 * H + x1;
        s_o10[tid] = y1 * H + x0;
        s_o11[tid] = y1 * H + x1;
        s_w00[tid] = (1.f - wx) * (1.f - wy);
        s_w01[tid] = wx * (1.f - wy);
        s_w10[tid] = (1.f - wx) * wy;
        s_w11[tid] = wx * wy;
    }
    __syncthreads();

    const int warp = tid >> 5;
    const int lane = tid & 31;

    // Register-cache the (up to) two points this lane owns.
    const int  pA = lane;
    const bool hasB = (32 + lane) < NPTS;
    const int  pB = hasB ? 32 + lane : 0;

    const int   a00 = s_o00[pA], a01 = s_o01[pA], a10 = s_o10[pA], a11 = s_o11[pA];
    const float wa00 = s_w00[pA], wa01 = s_w01[pA], wa10 = s_w10[pA], wa11 = s_w11[pA];
    const int   b00 = s_o00[pB], b01 = s_o01[pB], b10 = s_o10[pB], b11 = s_o11[pB];
    const float wb00 = s_w00[pB], wb01 = s_w01[pB], wb10 = s_w10[pB], wb11 = s_w11[pB];

    // Channel loop over this CTA's half: c = cbase + warp + 8k, unrolled x2.
    const int cbase = half * CPER;
    const int cend  = cbase + CPER;
    #pragma unroll 1
    for (int c = cbase + warp; c < cend; c += 16) {
        const float* pl0 = base + (size_t)c * HW;
        const float* pl1 = pl0 + (size_t)8 * HW;
        float* o0 = op + c * NPTS;
        float* o1 = o0 + 8 * NPTS;

        const float v0a00 = __ldg(pl0 + a00), v0a01 = __ldg(pl0 + a01);
        const float v0a10 = __ldg(pl0 + a10), v0a11 = __ldg(pl0 + a11);
        const float v1a00 = __ldg(pl1 + a00), v1a01 = __ldg(pl1 + a01);
        const float v1a10 = __ldg(pl1 + a10), v1a11 = __ldg(pl1 + a11);

        float v0b00 = 0.f, v0b01 = 0.f, v0b10 = 0.f, v0b11 = 0.f;
        float v1b00 = 0.f, v1b01 = 0.f, v1b10 = 0.f, v1b11 = 0.f;
        if (hasB) {
            v0b00 = __ldg(pl0 + b00); v0b01 = __ldg(pl0 + b01);
            v0b10 = __ldg(pl0 + b10); v0b11 = __ldg(pl0 + b11);
            v1b00 = __ldg(pl1 + b00); v1b01 = __ldg(pl1 + b01);
            v1b10 = __ldg(pl1 + b10); v1b11 = __ldg(pl1 + b11);
        }

        o0[pA] = v0a00 * wa00 + v0a01 * wa01 + v0a10 * wa10 + v0a11 * wa11;
        o1[pA] = v1a00 * wa00 + v1a01 * wa01 + v1a10 * wa10 + v1a11 * wa11;
        if (hasB) {
            o0[pB] = v0b00 * wb00 + v0b01 * wb01 + v0b10 * wb10 + v0b11 * wb11;
            o1[pB] = v1b00 * wb00 + v1b01 * wb01 + v1b10 * wb10 + v1b11 * wb11;
        }
    }
}

extern "C" void kernel_launch(void* const* d_in, const int* in_sizes, int n_in,
                              void* d_out, int out_size) {
    const float* f0 = (const float*)d_in[0];
    const float* f1 = (const float*)d_in[1];
    const float* f2 = (const float*)d_in[2];
    const float* f3 = (const float*)d_in[3];
    const float* rois = (const float*)d_in[4];
    const int* levels = (const int*)d_in[5];
    float* out = (float*)d_out;

    const int B = in_sizes[0] / (256 * 256 * 256);
    const int total = in_sizes[5];        // B*N rois
    const int N = total / (B > 0 ? B : 1);

    oriented_roi_align_kernel<<<total * CSPLIT, 256>>>(f0, f1, f2, f3, rois, levels, out, N);
}